// round 13
// baseline (speedup 1.0000x reference)
#include <cuda_runtime.h>
#include <cuda_fp16.h>
#include <cstdint>

#define D_FEAT      64
#define N_NODES_MAX 100000
#define EPS         64            // edges per 16-thread group (R9-proven)
#define SUBS        8             // groups per block
#define EPB         (EPS * SUBS)  // 512 edges per block
#define THREADS     128
#define MINBLOCKS   9             // force regs<=56 -> 36 warps/SM (was 64 -> 32)

// Scratch (allocation-free). Intermediate hop in fp16.
__device__ __half g_tmp[(size_t)N_NODES_MAX * D_FEAT];

__device__ __forceinline__ void red_add_v4(float* p, float4 a) {
    asm volatile("red.global.add.v4.f32 [%0], {%1, %2, %3, %4};"
                 :: "l"(p), "f"(a.x), "f"(a.y), "f"(a.z), "f"(a.w)
                 : "memory");
}
__device__ __forceinline__ void red_add_h2(uint32_t* p, float2 v) {
    __half2 h = __float22half2_rn(v);
    asm volatile("red.global.add.noftz.f16x2 [%0], %1;"
                 :: "l"(p), "r"(*reinterpret_cast<uint32_t*>(&h))
                 : "memory");
}

// ---- per-dtype feature row helpers (each d4-thread owns 4 features) ----
template <bool HALF>
__device__ __forceinline__ float4 ld_feat(const char* p) {
    if (HALF) {
        uint2 r = *reinterpret_cast<const uint2*>(p);
        float2 a = __half22float2(*reinterpret_cast<__half2*>(&r.x));
        float2 b = __half22float2(*reinterpret_cast<__half2*>(&r.y));
        return make_float4(a.x, a.y, b.x, b.y);
    } else {
        return *reinterpret_cast<const float4*>(p);
    }
}
template <bool HALF>
__device__ __forceinline__ void st_feat(char* p, float4 v) {
    if (HALF) {
        uint2 u;
        __half2 h0 = __float22half2_rn(make_float2(v.x, v.y));
        __half2 h1 = __float22half2_rn(make_float2(v.z, v.w));
        u.x = *reinterpret_cast<uint32_t*>(&h0);
        u.y = *reinterpret_cast<uint32_t*>(&h1);
        *reinterpret_cast<uint2*>(p) = u;
    } else {
        *reinterpret_cast<float4*>(p) = v;
    }
}
template <bool HALF>
__device__ __forceinline__ void red_feat(char* p, float4 v) {
    if (HALF) {
        uint32_t* u = reinterpret_cast<uint32_t*>(p);
        red_add_h2(u + 0, make_float2(v.x, v.y));
        red_add_h2(u + 1, make_float2(v.z, v.w));
    } else {
        red_add_v4(reinterpret_cast<float*>(p), v);
    }
}

// R9-proven sorted-row SpMM: interior runs -> exclusive STG, boundary runs ->
// red.add into pre-zeroed dst. 8 gathers in flight per inner iteration.
// Register-capped to raise occupancy (latency-bound per R9 ncu).
template <bool SRC_H, bool DST_H>
__global__ void __launch_bounds__(THREADS, MINBLOCKS)
spmm_kernel(const char* __restrict__ src,
            const int*  __restrict__ erow,
            const int*  __restrict__ ecol,
            const float* __restrict__ eval,
            char*       __restrict__ dst,
            int n_edges) {
    constexpr int SRC_RB = SRC_H ? 128 : 256;
    constexpr int DST_RB = DST_H ? 128 : 256;
    constexpr int SRC_TB = SRC_H ? 8 : 16;
    constexpr int DST_TB = DST_H ? 8 : 16;

    __shared__ alignas(16) int   s_row[EPB];
    __shared__ alignas(16) int   s_off[EPB];   // col * SRC_RB
    __shared__ alignas(16) float s_val[EPB];

    const int base = blockIdx.x * EPB;
    const int tid  = threadIdx.x;

    // Vectorized staging; pad with last valid row, val = 0.
    {
        const int i = tid * 4;
        const int e = base + i;
        if (e + 3 < n_edges) {
            int4   r = *reinterpret_cast<const int4*>(erow + e);
            int4   c = *reinterpret_cast<const int4*>(ecol + e);
            float4 v = *reinterpret_cast<const float4*>(eval + e);
            c.x *= SRC_RB; c.y *= SRC_RB; c.z *= SRC_RB; c.w *= SRC_RB;
            *reinterpret_cast<int4*>(s_row + i)   = r;
            *reinterpret_cast<int4*>(s_off + i)   = c;
            *reinterpret_cast<float4*>(s_val + i) = v;
        } else {
            #pragma unroll
            for (int k = 0; k < 4; k++) {
                int ee   = e + k;
                int esrc = min(ee, n_edges - 1);
                int in   = (ee < n_edges);
                s_row[i + k] = erow[esrc];
                s_off[i + k] = in ? ecol[esrc] * SRC_RB : 0;
                s_val[i + k] = in ? eval[esrc] : 0.f;
            }
        }
    }
    __syncthreads();

    const int d4  = tid & 15;
    const int sub = tid >> 4;
    const int off = sub * EPS;
    const char* sp = src + d4 * SRC_TB;
    char*       dp = dst + d4 * DST_TB;

    int    cur       = s_row[off];
    int    run_start = 0;
    float4 acc       = make_float4(0.f, 0.f, 0.f, 0.f);

    for (int ib = 0; ib < EPS; ib += 8) {
        const int4   ra = *reinterpret_cast<const int4*>(s_row + off + ib);
        const int4   rb = *reinterpret_cast<const int4*>(s_row + off + ib + 4);
        const int4   ca = *reinterpret_cast<const int4*>(s_off + off + ib);
        const int4   cb = *reinterpret_cast<const int4*>(s_off + off + ib + 4);
        const float4 va = *reinterpret_cast<const float4*>(s_val + off + ib);
        const float4 vb = *reinterpret_cast<const float4*>(s_val + off + ib + 4);

        // 8 gathers in flight (MLP = 8)
        const float4 g0 = ld_feat<SRC_H>(sp + ca.x);
        const float4 g1 = ld_feat<SRC_H>(sp + ca.y);
        const float4 g2 = ld_feat<SRC_H>(sp + ca.z);
        const float4 g3 = ld_feat<SRC_H>(sp + ca.w);
        const float4 g4 = ld_feat<SRC_H>(sp + cb.x);
        const float4 g5 = ld_feat<SRC_H>(sp + cb.y);
        const float4 g6 = ld_feat<SRC_H>(sp + cb.z);
        const float4 g7 = ld_feat<SRC_H>(sp + cb.w);

        #define STEP(R, V, G, IDX)                                           \
        do {                                                                 \
            if ((R) != cur) {                                                \
                char* p = dp + (size_t)cur * DST_RB;                         \
                if (run_start > 0) {                                         \
                    st_feat<DST_H>(p, acc);       /* exclusive interior */   \
                } else {                                                     \
                    red_feat<DST_H>(p, acc);      /* boundary */             \
                }                                                            \
                acc = make_float4(0.f, 0.f, 0.f, 0.f);                       \
                cur = (R);                                                   \
                run_start = (IDX);                                           \
            }                                                                \
            acc.x += (V) * (G).x;                                            \
            acc.y += (V) * (G).y;                                            \
            acc.z += (V) * (G).z;                                            \
            acc.w += (V) * (G).w;                                            \
        } while (0)

        STEP(ra.x, va.x, g0, ib + 0);
        STEP(ra.y, va.y, g1, ib + 1);
        STEP(ra.z, va.z, g2, ib + 2);
        STEP(ra.w, va.w, g3, ib + 3);
        STEP(rb.x, vb.x, g4, ib + 4);
        STEP(rb.y, vb.y, g5, ib + 5);
        STEP(rb.z, vb.z, g6, ib + 6);
        STEP(rb.w, vb.w, g7, ib + 7);
        #undef STEP
    }

    // Final run may continue into the next group -> always atomic.
    red_feat<DST_H>(dp + (size_t)cur * DST_RB, acc);
}

extern "C" void kernel_launch(void* const* d_in, const int* in_sizes, int n_in,
                              void* d_out, int out_size) {
    const char*  x    = (const char*) d_in[0];
    const int*   erow = (const int*)  d_in[1];
    const int*   ecol = (const int*)  d_in[2];
    const float* eval = (const float*)d_in[3];
    char*        out  = (char*)d_out;

    const int n_edges = in_sizes[1];
    const int n_rows  = out_size / D_FEAT;
    const int n_elems = n_rows * D_FEAT;

    void* tmp_sym = nullptr;
    cudaGetSymbolAddress(&tmp_sym, g_tmp);
    char* tmp = (char*)tmp_sym;

    const int sgrid = (n_edges + EPB - 1) / EPB;

    // Host-side resources for the fork/join (no device memory involved).
    static cudaStream_t side = nullptr;
    static cudaEvent_t  ev_fork = nullptr, ev_join = nullptr;
    if (!side) {
        cudaStreamCreateWithFlags(&side, cudaStreamNonBlocking);
        cudaEventCreateWithFlags(&ev_fork, cudaEventDisableTiming);
        cudaEventCreateWithFlags(&ev_join, cudaEventDisableTiming);
    }

    // Critical path: zero tmp (needed by hop 1's boundary red.adds).
    cudaMemsetAsync(tmp, 0, (size_t)n_elems * 2);

    // Fork: zero out on the side stream, overlapping hop 1.
    cudaEventRecord(ev_fork, 0);
    cudaStreamWaitEvent(side, ev_fork, 0);
    cudaMemsetAsync(out, 0, (size_t)n_elems * 4, side);
    cudaEventRecord(ev_join, side);

    // Hop 1: tmp(fp16) = A @ x(fp32)   (overlaps memset(out))
    spmm_kernel<false, true><<<sgrid, THREADS>>>(x, erow, ecol, eval, tmp, n_edges);

    // Join: out must be zeroed before hop 2's red.adds.
    cudaStreamWaitEvent(0, ev_join, 0);

    // Hop 2: out(fp32) = A @ tmp(fp16)
    spmm_kernel<true, false><<<sgrid, THREADS>>>(tmp, erow, ecol, eval, out, n_edges);
}

// round 14
// speedup vs baseline: 1.4365x; 1.4365x over previous
#include <cuda_runtime.h>
#include <cuda_fp16.h>
#include <cstdint>

#define D_FEAT      64
#define N_NODES_MAX 100000
#define EPS         64            // edges per 16-thread group (R9-proven)
#define SUBS        8             // groups per block
#define EPB         (EPS * SUBS)  // 512 edges per block
#define THREADS     128

// Scratch (allocation-free). Intermediate hop in fp16.
__device__ __half g_tmp[(size_t)N_NODES_MAX * D_FEAT];

__device__ __forceinline__ void red_add_v4(float* p, float4 a) {
    asm volatile("red.global.add.v4.f32 [%0], {%1, %2, %3, %4};"
                 :: "l"(p), "f"(a.x), "f"(a.y), "f"(a.z), "f"(a.w)
                 : "memory");
}
__device__ __forceinline__ void red_add_h2(uint32_t* p, float2 v) {
    __half2 h = __float22half2_rn(v);
    asm volatile("red.global.add.noftz.f16x2 [%0], %1;"
                 :: "l"(p), "r"(*reinterpret_cast<uint32_t*>(&h))
                 : "memory");
}

// ---- raw gather type: fp16 rows stay packed (2 regs) until use ----
template <bool HALF> struct RawFeat            { using T = float4; };
template <>          struct RawFeat<true>      { using T = uint2;  };

template <bool HALF>
__device__ __forceinline__ typename RawFeat<HALF>::T ld_raw(const char* p) {
    return *reinterpret_cast<const typename RawFeat<HALF>::T*>(p);
}
__device__ __forceinline__ float4 to_f4(float4 g) { return g; }
__device__ __forceinline__ float4 to_f4(uint2 r) {
    float2 a = __half22float2(*reinterpret_cast<__half2*>(&r.x));
    float2 b = __half22float2(*reinterpret_cast<__half2*>(&r.y));
    return make_float4(a.x, a.y, b.x, b.y);
}

template <bool HALF>
__device__ __forceinline__ void st_feat(char* p, float4 v) {
    if (HALF) {
        uint2 u;
        __half2 h0 = __float22half2_rn(make_float2(v.x, v.y));
        __half2 h1 = __float22half2_rn(make_float2(v.z, v.w));
        u.x = *reinterpret_cast<uint32_t*>(&h0);
        u.y = *reinterpret_cast<uint32_t*>(&h1);
        *reinterpret_cast<uint2*>(p) = u;
    } else {
        *reinterpret_cast<float4*>(p) = v;
    }
}
template <bool HALF>
__device__ __forceinline__ void red_feat(char* p, float4 v) {
    if (HALF) {
        uint32_t* u = reinterpret_cast<uint32_t*>(p);
        red_add_h2(u + 0, make_float2(v.x, v.y));
        red_add_h2(u + 1, make_float2(v.z, v.w));
    } else {
        red_add_v4(reinterpret_cast<float*>(p), v);
    }
}

// R9-proven sorted-row SpMM: interior runs -> exclusive STG, boundary runs ->
// red.add into pre-zeroed dst. 8 gathers in flight, held in RAW (packed) form
// and converted at use to halve live register pressure on the fp16-src hop.
template <bool SRC_H, bool DST_H>
__global__ void __launch_bounds__(THREADS)
spmm_kernel(const char* __restrict__ src,
            const int*  __restrict__ erow,
            const int*  __restrict__ ecol,
            const float* __restrict__ eval,
            char*       __restrict__ dst,
            int n_edges) {
    constexpr int SRC_RB = SRC_H ? 128 : 256;
    constexpr int DST_RB = DST_H ? 128 : 256;
    constexpr int SRC_TB = SRC_H ? 8 : 16;
    constexpr int DST_TB = DST_H ? 8 : 16;

    __shared__ alignas(16) int   s_row[EPB];
    __shared__ alignas(16) int   s_off[EPB];   // col * SRC_RB
    __shared__ alignas(16) float s_val[EPB];

    const int base = blockIdx.x * EPB;
    const int tid  = threadIdx.x;

    // Vectorized staging; pad with last valid row, val = 0.
    {
        const int i = tid * 4;
        const int e = base + i;
        if (e + 3 < n_edges) {
            int4   r = *reinterpret_cast<const int4*>(erow + e);
            int4   c = *reinterpret_cast<const int4*>(ecol + e);
            float4 v = *reinterpret_cast<const float4*>(eval + e);
            c.x *= SRC_RB; c.y *= SRC_RB; c.z *= SRC_RB; c.w *= SRC_RB;
            *reinterpret_cast<int4*>(s_row + i)   = r;
            *reinterpret_cast<int4*>(s_off + i)   = c;
            *reinterpret_cast<float4*>(s_val + i) = v;
        } else {
            #pragma unroll
            for (int k = 0; k < 4; k++) {
                int ee   = e + k;
                int esrc = min(ee, n_edges - 1);
                int in   = (ee < n_edges);
                s_row[i + k] = erow[esrc];
                s_off[i + k] = in ? ecol[esrc] * SRC_RB : 0;
                s_val[i + k] = in ? eval[esrc] : 0.f;
            }
        }
    }
    __syncthreads();

    const int d4  = tid & 15;
    const int sub = tid >> 4;
    const int off = sub * EPS;
    const char* sp = src + d4 * SRC_TB;
    char*       dp = dst + d4 * DST_TB;

    int    cur       = s_row[off];
    int    run_start = 0;
    float4 acc       = make_float4(0.f, 0.f, 0.f, 0.f);

    using Raw = typename RawFeat<SRC_H>::T;

    for (int ib = 0; ib < EPS; ib += 8) {
        const int4   ra = *reinterpret_cast<const int4*>(s_row + off + ib);
        const int4   rb = *reinterpret_cast<const int4*>(s_row + off + ib + 4);
        const int4   ca = *reinterpret_cast<const int4*>(s_off + off + ib);
        const int4   cb = *reinterpret_cast<const int4*>(s_off + off + ib + 4);
        const float4 va = *reinterpret_cast<const float4*>(s_val + off + ib);
        const float4 vb = *reinterpret_cast<const float4*>(s_val + off + ib + 4);

        // 8 gathers in flight (MLP = 8), kept packed until use.
        const Raw g0 = ld_raw<SRC_H>(sp + ca.x);
        const Raw g1 = ld_raw<SRC_H>(sp + ca.y);
        const Raw g2 = ld_raw<SRC_H>(sp + ca.z);
        const Raw g3 = ld_raw<SRC_H>(sp + ca.w);
        const Raw g4 = ld_raw<SRC_H>(sp + cb.x);
        const Raw g5 = ld_raw<SRC_H>(sp + cb.y);
        const Raw g6 = ld_raw<SRC_H>(sp + cb.z);
        const Raw g7 = ld_raw<SRC_H>(sp + cb.w);

        #define STEP(R, V, G, IDX)                                           \
        do {                                                                 \
            if ((R) != cur) {                                                \
                char* p = dp + (size_t)cur * DST_RB;                         \
                if (run_start > 0) {                                         \
                    st_feat<DST_H>(p, acc);       /* exclusive interior */   \
                } else {                                                     \
                    red_feat<DST_H>(p, acc);      /* boundary */             \
                }                                                            \
                acc = make_float4(0.f, 0.f, 0.f, 0.f);                       \
                cur = (R);                                                   \
                run_start = (IDX);                                           \
            }                                                                \
            {                                                                \
                const float4 gf = to_f4(G);      /* convert at use */        \
                acc.x += (V) * gf.x;                                         \
                acc.y += (V) * gf.y;                                         \
                acc.z += (V) * gf.z;                                         \
                acc.w += (V) * gf.w;                                         \
            }                                                                \
        } while (0)

        STEP(ra.x, va.x, g0, ib + 0);
        STEP(ra.y, va.y, g1, ib + 1);
        STEP(ra.z, va.z, g2, ib + 2);
        STEP(ra.w, va.w, g3, ib + 3);
        STEP(rb.x, vb.x, g4, ib + 4);
        STEP(rb.y, vb.y, g5, ib + 5);
        STEP(rb.z, vb.z, g6, ib + 6);
        STEP(rb.w, vb.w, g7, ib + 7);
        #undef STEP
    }

    // Final run may continue into the next group -> always atomic.
    red_feat<DST_H>(dp + (size_t)cur * DST_RB, acc);
}

extern "C" void kernel_launch(void* const* d_in, const int* in_sizes, int n_in,
                              void* d_out, int out_size) {
    const char*  x    = (const char*) d_in[0];
    const int*   erow = (const int*)  d_in[1];
    const int*   ecol = (const int*)  d_in[2];
    const float* eval = (const float*)d_in[3];
    char*        out  = (char*)d_out;

    const int n_edges = in_sizes[1];
    const int n_rows  = out_size / D_FEAT;
    const int n_elems = n_rows * D_FEAT;

    void* tmp_sym = nullptr;
    cudaGetSymbolAddress(&tmp_sym, g_tmp);
    char* tmp = (char*)tmp_sym;

    const int sgrid = (n_edges + EPB - 1) / EPB;

    // Host-side resources for the fork/join (no device memory involved).
    static cudaStream_t side = nullptr;
    static cudaEvent_t  ev_fork = nullptr, ev_join = nullptr;
    if (!side) {
        cudaStreamCreateWithFlags(&side, cudaStreamNonBlocking);
        cudaEventCreateWithFlags(&ev_fork, cudaEventDisableTiming);
        cudaEventCreateWithFlags(&ev_join, cudaEventDisableTiming);
    }

    // Critical path: zero tmp (needed by hop 1's boundary red.adds).
    cudaMemsetAsync(tmp, 0, (size_t)n_elems * 2);

    // Fork: zero out on the side stream, overlapping hop 1.
    cudaEventRecord(ev_fork, 0);
    cudaStreamWaitEvent(side, ev_fork, 0);
    cudaMemsetAsync(out, 0, (size_t)n_elems * 4, side);
    cudaEventRecord(ev_join, side);

    // Hop 1: tmp(fp16) = A @ x(fp32)   (overlaps memset(out))
    spmm_kernel<false, true><<<sgrid, THREADS>>>(x, erow, ecol, eval, tmp, n_edges);

    // Join: out must be zeroed before hop 2's red.adds.
    cudaStreamWaitEvent(0, ev_join, 0);

    // Hop 2: out(fp32) = A @ tmp(fp16)
    spmm_kernel<true, false><<<sgrid, THREADS>>>(tmp, erow, ecol, eval, out, n_edges);
}